// round 1
// baseline (speedup 1.0000x reference)
#include <cuda_runtime.h>
#include <math.h>

#define BATCH 2
#define NC 8
#define NE 16
#define NSEG 17
#define DD 64
#define HH 128
#define WW 128
#define NVOX (DD*HH*WW)      /* 1048576 per batch */
#define NTOT (BATCH*NVOX)

// ---------------- scratch (device globals; no allocation) ----------------
__device__ float g_w[NTOT];
__device__ float g_nll;
__device__ float g_cardp[BATCH][NC];
__device__ float g_inter[BATCH][NC];
__device__ float g_cardg[BATCH][NC];
__device__ float g_wsum[BATCH][NSEG];
__device__ float g_cnt[BATCH][NSEG];
__device__ float g_cnum[BATCH][NSEG][NE];
__device__ float g_centers[BATCH][NSEG][NE];
__device__ float g_pull[BATCH][NSEG];
__device__ float g_push[BATCH];
__device__ float g_normv[BATCH];
__device__ float g_val[BATCH];

// ---------------- zero accumulators ----------------
__global__ void zero_kernel() {
    int t = blockIdx.x * blockDim.x + threadIdx.x;
    if (t < BATCH*NC) {
        (&g_cardp[0][0])[t] = 0.f;
        (&g_inter[0][0])[t] = 0.f;
        (&g_cardg[0][0])[t] = 0.f;
    }
    if (t < BATCH*NSEG) {
        (&g_wsum[0][0])[t] = 0.f;
        (&g_cnt[0][0])[t]  = 0.f;
        (&g_pull[0][0])[t] = 0.f;
    }
    if (t < BATCH*NSEG*NE) (&g_cnum[0][0][0])[t] = 0.f;
    if (t < BATCH) { g_push[t] = 0.f; g_normv[t] = 0.f; g_val[t] = 0.f; }
    if (t == 0) g_nll = 0.f;
}

// ---------------- CE + Dice fused pass over sem_logits ----------------
__global__ void __launch_bounds__(256) ce_dice_kernel(const float* __restrict__ logits,
                                                      const int* __restrict__ cls) {
    int b = blockIdx.y;
    const float4* lb = (const float4*)(logits + (size_t)b * NC * NVOX);
    const int4*   cb = (const int4*)(cls + (size_t)b * NVOX);

    float r_nll = 0.f;
    float r_cardp[NC], r_inter[NC], r_cardg[NC];
#pragma unroll
    for (int c = 0; c < NC; c++) { r_cardp[c]=0.f; r_inter[c]=0.f; r_cardg[c]=0.f; }

    int stride = gridDim.x * blockDim.x;
    for (int i = blockIdx.x * blockDim.x + threadIdx.x; i < NVOX/4; i += stride) {
        float4 x4[NC];
#pragma unroll
        for (int c = 0; c < NC; c++) x4[c] = lb[(size_t)c * (NVOX/4) + i];
        int4 t4 = cb[i];
#pragma unroll
        for (int j = 0; j < 4; j++) {
            float xv[NC];
#pragma unroll
            for (int c = 0; c < NC; c++)
                xv[c] = (j==0) ? x4[c].x : (j==1) ? x4[c].y : (j==2) ? x4[c].z : x4[c].w;
            int t = (j==0) ? t4.x : (j==1) ? t4.y : (j==2) ? t4.z : t4.w;

            float m = xv[0];
#pragma unroll
            for (int c = 1; c < NC; c++) m = fmaxf(m, xv[c]);
            float ex[NC]; float s = 0.f;
#pragma unroll
            for (int c = 0; c < NC; c++) { ex[c] = __expf(xv[c] - m); s += ex[c]; }
            float inv = 1.0f / s;
            float lse = m + __logf(s);
#pragma unroll
            for (int c = 0; c < NC; c++) {
                float p = ex[c] * inv;
                r_cardp[c] += p;
                if (t == c) {
                    r_inter[c] += p;
                    r_cardg[c] += 1.f;
                    r_nll += lse - xv[c];
                }
            }
        }
    }

    // reduce 25 values: warp shuffle -> shared -> global atomic
    __shared__ float s_acc[25];
    if (threadIdx.x < 25) s_acc[threadIdx.x] = 0.f;
    __syncthreads();
    float vals[25];
    vals[0] = r_nll;
#pragma unroll
    for (int c = 0; c < NC; c++) { vals[1+c]=r_cardp[c]; vals[9+c]=r_inter[c]; vals[17+c]=r_cardg[c]; }
#pragma unroll
    for (int k = 0; k < 25; k++) {
        float v = vals[k];
#pragma unroll
        for (int o = 16; o; o >>= 1) v += __shfl_xor_sync(0xffffffffu, v, o);
        if ((threadIdx.x & 31) == 0) atomicAdd(&s_acc[k], v);
    }
    __syncthreads();
    int t = threadIdx.x;
    if (t == 0)        atomicAdd(&g_nll, s_acc[0]);
    else if (t < 9)    atomicAdd(&g_cardp[b][t-1],  s_acc[t]);
    else if (t < 17)   atomicAdd(&g_inter[b][t-9],  s_acc[t]);
    else if (t < 25)   atomicAdd(&g_cardg[b][t-17], s_acc[t]);
}

// ---------------- boundary weight (3x3x3 any-neighbor-differs) ----------------
__global__ void boundary_kernel(const int* __restrict__ lab) {
    int idx = blockIdx.x * blockDim.x + threadIdx.x;
    if (idx >= NTOT) return;
    int b = idx >> 20;            // / NVOX
    int v = idx & (NVOX - 1);
    int d = v >> 14;              // / (HH*WW)
    int r = v & 16383;
    int h = r >> 7;
    int x = r & 127;
    const int* Lb = lab + (size_t)b * NVOX;
    int c0 = Lb[v];
    bool diff = false;
#pragma unroll
    for (int dd = -1; dd <= 1; dd++) {
        int zd = min(max(d + dd, 0), DD - 1);
#pragma unroll
        for (int dh = -1; dh <= 1; dh++) {
            int zh = min(max(h + dh, 0), HH - 1);
#pragma unroll
            for (int dx = -1; dx <= 1; dx++) {
                int zx = min(max(x + dx, 0), WW - 1);
                diff |= (Lb[(zd << 14) + (zh << 7) + zx] != c0);
            }
        }
    }
    g_w[idx] = diff ? 10.f : 1.f;   // 1 + boundary*(W_EDGE-1)
}

// ---------------- pass A: weighted segment sums ----------------
__global__ void __launch_bounds__(256) segstat_kernel(const float* __restrict__ embed,
                                                      const int* __restrict__ lab) {
    int b = blockIdx.y;
    __shared__ float s_wsum[NSEG], s_cnt[NSEG];
    __shared__ float s_cnum[NSEG][NE + 1];    // pad to 17: kill 2-bank pattern
    for (int j = threadIdx.x; j < NSEG; j += blockDim.x) { s_wsum[j]=0.f; s_cnt[j]=0.f; }
    for (int j = threadIdx.x; j < NSEG*(NE+1); j += blockDim.x) (&s_cnum[0][0])[j] = 0.f;
    __syncthreads();

    const float4* eb = (const float4*)(embed + (size_t)b * NE * NVOX);
    const int4*   Lb = (const int4*)(lab + (size_t)b * NVOX);
    const float4* wb = (const float4*)(g_w + (size_t)b * NVOX);

    int stride = gridDim.x * blockDim.x;
    for (int i = blockIdx.x * blockDim.x + threadIdx.x; i < NVOX/4; i += stride) {
        float4 e4[NE];
#pragma unroll
        for (int c = 0; c < NE; c++) e4[c] = eb[(size_t)c * (NVOX/4) + i];
        int4 l4 = Lb[i];
        float4 w4 = wb[i];
#pragma unroll
        for (int j = 0; j < 4; j++) {
            int   l  = (j==0) ? l4.x : (j==1) ? l4.y : (j==2) ? l4.z : l4.w;
            float wv = (j==0) ? w4.x : (j==1) ? w4.y : (j==2) ? w4.z : w4.w;
            l = min(max(l, 0), NSEG - 1);
            atomicAdd(&s_wsum[l], wv);
            atomicAdd(&s_cnt[l], 1.f);
#pragma unroll
            for (int c = 0; c < NE; c++) {
                float ev = (j==0) ? e4[c].x : (j==1) ? e4[c].y : (j==2) ? e4[c].z : e4[c].w;
                atomicAdd(&s_cnum[l][c], ev * wv);
            }
        }
    }
    __syncthreads();
    for (int j = threadIdx.x; j < NSEG; j += blockDim.x) {
        atomicAdd(&g_wsum[b][j], s_wsum[j]);
        atomicAdd(&g_cnt[b][j],  s_cnt[j]);
    }
    for (int j = threadIdx.x; j < NSEG*NE; j += blockDim.x)
        atomicAdd(&g_cnum[b][j / NE][j % NE], s_cnum[j / NE][j % NE]);
}

// ---------------- centers + push + norm (tiny) ----------------
__global__ void centers_kernel() {
    int b = blockIdx.x;
    __shared__ float sc[NSEG][NE + 1];
    __shared__ int   s_present[NSEG];
    __shared__ float s_push, s_norm;
    __shared__ int   s_np;
    int tid = threadIdx.x;
    if (tid == 0) { s_push = 0.f; s_norm = 0.f; s_np = 0; }
    for (int j = tid; j < NSEG*NE; j += blockDim.x) {
        int k = j / NE, c = j % NE;
        float cen = g_cnum[b][k][c] / (g_wsum[b][k] + 1e-8f);
        g_centers[b][k][c] = cen;
        sc[k][c] = cen;
    }
    for (int k = tid; k < NSEG; k += blockDim.x) s_present[k] = (g_cnt[b][k] > 0.f) ? 1 : 0;
    __syncthreads();
    if (tid == 0) {
        int np = 0;
        for (int k = 1; k < NSEG; k++) np += s_present[k];
        s_np = np;
    }
    // push over 120 pairs (i<j in 1..16)
    float pacc = 0.f;
    for (int p = tid; p < 120; p += blockDim.x) {
        int i = 1, rem = p;
        while (rem >= (NSEG - 1) - i) { rem -= (NSEG - 1) - i; i++; }
        int jj = i + 1 + rem;
        float ds = 0.f;
#pragma unroll
        for (int c = 0; c < NE; c++) { float dv = sc[i][c] - sc[jj][c]; ds += dv * dv; }
        float pw = sqrtf(ds);
        float tt = fmaxf(3.0f - pw, 0.f);       // 2*DELTA_D = 3.0
        if (s_present[i] && s_present[jj]) pacc += tt * tt;
    }
    atomicAdd(&s_push, pacc);
    float nacc = 0.f;
    for (int k = 1 + tid; k < NSEG; k += blockDim.x) {
        if (s_present[k]) {
            float ds = 0.f;
#pragma unroll
            for (int c = 0; c < NE; c++) ds += sc[k][c] * sc[k][c];
            nacc += sqrtf(ds);
        }
    }
    atomicAdd(&s_norm, nacc);
    __syncthreads();
    if (tid == 0) {
        float np = (float)s_np;
        float npairs = np * (np - 1.f) * 0.5f;
        g_push[b]  = (npairs > 0.f) ? s_push / fmaxf(npairs, 1.f) : 0.f;
        g_normv[b] = (np > 0.f)     ? s_norm / fmaxf(np, 1.f)     : 0.f;
        g_val[b]   = (np > 0.f) ? 1.f : 0.f;
    }
}

// ---------------- pass B: pull ----------------
__global__ void __launch_bounds__(256) pull_kernel(const float* __restrict__ embed,
                                                   const int* __restrict__ lab) {
    int b = blockIdx.y;
    __shared__ float sc[NSEG][NE + 1];
    __shared__ float s_pull[NSEG];
    for (int j = threadIdx.x; j < NSEG*NE; j += blockDim.x)
        sc[j / NE][j % NE] = g_centers[b][j / NE][j % NE];
    for (int j = threadIdx.x; j < NSEG; j += blockDim.x) s_pull[j] = 0.f;
    __syncthreads();

    const float4* eb = (const float4*)(embed + (size_t)b * NE * NVOX);
    const int4*   Lb = (const int4*)(lab + (size_t)b * NVOX);
    const float4* wb = (const float4*)(g_w + (size_t)b * NVOX);

    int stride = gridDim.x * blockDim.x;
    for (int i = blockIdx.x * blockDim.x + threadIdx.x; i < NVOX/4; i += stride) {
        float4 e4[NE];
#pragma unroll
        for (int c = 0; c < NE; c++) e4[c] = eb[(size_t)c * (NVOX/4) + i];
        int4 l4 = Lb[i];
        float4 w4 = wb[i];
#pragma unroll
        for (int j = 0; j < 4; j++) {
            int   l  = (j==0) ? l4.x : (j==1) ? l4.y : (j==2) ? l4.z : l4.w;
            float wv = (j==0) ? w4.x : (j==1) ? w4.y : (j==2) ? w4.z : w4.w;
            l = min(max(l, 0), NSEG - 1);
            float ds = 0.f;
#pragma unroll
            for (int c = 0; c < NE; c++) {
                float ev = (j==0) ? e4[c].x : (j==1) ? e4[c].y : (j==2) ? e4[c].z : e4[c].w;
                float dv = ev - sc[l][c];
                ds += dv * dv;
            }
            float dist = sqrtf(ds);
            float tt = fmaxf(dist - 0.5f, 0.f);   // DELTA_V
            atomicAdd(&s_pull[l], tt * tt * wv);
        }
    }
    __syncthreads();
    for (int j = threadIdx.x; j < NSEG; j += blockDim.x)
        atomicAdd(&g_pull[b][j], s_pull[j]);
}

// ---------------- final combine ----------------
__global__ void final_kernel(float* __restrict__ out) {
    if (threadIdx.x != 0 || blockIdx.x != 0) return;
    float Nf = (float)NTOT;
    float ce = g_nll / Nf;

    float dsum = 0.f;
    for (int b = 0; b < BATCH; b++)
        for (int c = 0; c < NC; c++)
            dsum += (2.0f * g_inter[b][c] + 1e-5f) /
                    (g_cardp[b][c] + g_cardg[b][c] + 1e-5f);
    float dice = 1.0f - dsum / (float)(BATCH * NC);

    float lp = 0.f;
    for (int b = 0; b < BATCH; b++)
        for (int k = 1; k < NSEG; k++)
            if (g_cnt[b][k] > 0.f)
                lp += g_pull[b][k] / fmaxf(g_cnt[b][k], 1.f);

    float push = 0.f, nrm = 0.f, val = 0.f;
    for (int b = 0; b < BATCH; b++) { push += g_push[b]; nrm += g_normv[b]; val += g_val[b]; }

    float ins = (1.0f * lp + 1.0f * push + 0.001f * nrm) / fmaxf(val, 1.f);
    float sem = ce + dice;
    out[0] = sem + ins;
    out[1] = sem;
    out[2] = ce;
    out[3] = dice;
    out[4] = ins;
}

// ---------------- launch ----------------
extern "C" void kernel_launch(void* const* d_in, const int* in_sizes, int n_in,
                              void* d_out, int out_size) {
    const float* sem = (const float*)d_in[0];
    const float* emb = (const float*)d_in[1];
    const int*   cls = (const int*)d_in[2];
    const int*   lab = (const int*)d_in[3];
    float* out = (float*)d_out;

    zero_kernel<<<3, 256>>>();

    dim3 g1(296, BATCH);
    ce_dice_kernel<<<g1, 256>>>(sem, cls);

    boundary_kernel<<<NTOT / 256, 256>>>(lab);

    dim3 g2(296, BATCH);
    segstat_kernel<<<g2, 256>>>(emb, lab);

    centers_kernel<<<BATCH, 128>>>();

    pull_kernel<<<g2, 256>>>(emb, lab);

    final_kernel<<<1, 32>>>(out);
}

// round 2
// speedup vs baseline: 1.1721x; 1.1721x over previous
#include <cuda_runtime.h>
#include <math.h>

#define BATCH 2
#define NC 8
#define NE 16
#define NSEG 17
#define DD 64
#define HH 128
#define WW 128
#define NVOX (DD*HH*WW)      /* 1048576 per batch */
#define NTOT (BATCH*NVOX)

// ---------------- scratch (device globals; no allocation) ----------------
__device__ int   g_packed[NTOT];       // label | (boundary ? sign bit : 0)
__device__ float g_nll;
__device__ float g_cardp[BATCH][NC];
__device__ float g_inter[BATCH][NC];
__device__ float g_cardg[BATCH][NC];
__device__ float g_wsum[BATCH][NSEG];
__device__ float g_cnt[BATCH][NSEG];
__device__ float g_cnum[BATCH][NSEG][NE];
__device__ float g_centers[BATCH][NSEG][NE];
__device__ float g_pull[BATCH][NSEG];
__device__ float g_push[BATCH];
__device__ float g_normv[BATCH];
__device__ float g_val[BATCH];

// ---------------- zero accumulators ----------------
__global__ void zero_kernel() {
    int t = blockIdx.x * blockDim.x + threadIdx.x;
    if (t < BATCH*NC) {
        (&g_cardp[0][0])[t] = 0.f;
        (&g_inter[0][0])[t] = 0.f;
        (&g_cardg[0][0])[t] = 0.f;
    }
    if (t < BATCH*NSEG) {
        (&g_wsum[0][0])[t] = 0.f;
        (&g_cnt[0][0])[t]  = 0.f;
        (&g_pull[0][0])[t] = 0.f;
    }
    if (t < BATCH*NSEG*NE) (&g_cnum[0][0][0])[t] = 0.f;
    if (t < BATCH) { g_push[t] = 0.f; g_normv[t] = 0.f; g_val[t] = 0.f; }
    if (t == 0) g_nll = 0.f;
}

// ---------------- CE + Dice fused pass over sem_logits ----------------
__global__ void __launch_bounds__(256) ce_dice_kernel(const float* __restrict__ logits,
                                                      const int* __restrict__ cls) {
    int b = blockIdx.y;
    const float4* lb = (const float4*)(logits + (size_t)b * NC * NVOX);
    const int4*   cb = (const int4*)(cls + (size_t)b * NVOX);

    float r_nll = 0.f;
    float r_cardp[NC], r_inter[NC], r_cardg[NC];
#pragma unroll
    for (int c = 0; c < NC; c++) { r_cardp[c]=0.f; r_inter[c]=0.f; r_cardg[c]=0.f; }

    int stride = gridDim.x * blockDim.x;
    for (int i = blockIdx.x * blockDim.x + threadIdx.x; i < NVOX/4; i += stride) {
        float4 x4[NC];
#pragma unroll
        for (int c = 0; c < NC; c++) x4[c] = lb[(size_t)c * (NVOX/4) + i];
        int4 t4 = cb[i];
#pragma unroll
        for (int j = 0; j < 4; j++) {
            float xv[NC];
#pragma unroll
            for (int c = 0; c < NC; c++)
                xv[c] = (j==0) ? x4[c].x : (j==1) ? x4[c].y : (j==2) ? x4[c].z : x4[c].w;
            int t = (j==0) ? t4.x : (j==1) ? t4.y : (j==2) ? t4.z : t4.w;

            float m = xv[0];
#pragma unroll
            for (int c = 1; c < NC; c++) m = fmaxf(m, xv[c]);
            float ex[NC]; float s = 0.f;
#pragma unroll
            for (int c = 0; c < NC; c++) { ex[c] = __expf(xv[c] - m); s += ex[c]; }
            float inv = 1.0f / s;
            float lse = m + __logf(s);
#pragma unroll
            for (int c = 0; c < NC; c++) {
                float p = ex[c] * inv;
                r_cardp[c] += p;
                if (t == c) {
                    r_inter[c] += p;
                    r_cardg[c] += 1.f;
                    r_nll += lse - xv[c];
                }
            }
        }
    }

    __shared__ float s_acc[25];
    if (threadIdx.x < 25) s_acc[threadIdx.x] = 0.f;
    __syncthreads();
    float vals[25];
    vals[0] = r_nll;
#pragma unroll
    for (int c = 0; c < NC; c++) { vals[1+c]=r_cardp[c]; vals[9+c]=r_inter[c]; vals[17+c]=r_cardg[c]; }
#pragma unroll
    for (int k = 0; k < 25; k++) {
        float v = vals[k];
#pragma unroll
        for (int o = 16; o; o >>= 1) v += __shfl_xor_sync(0xffffffffu, v, o);
        if ((threadIdx.x & 31) == 0) atomicAdd(&s_acc[k], v);
    }
    __syncthreads();
    int t = threadIdx.x;
    if (t == 0)        atomicAdd(&g_nll, s_acc[0]);
    else if (t < 9)    atomicAdd(&g_cardp[b][t-1],  s_acc[t]);
    else if (t < 17)   atomicAdd(&g_inter[b][t-9],  s_acc[t]);
    else if (t < 25)   atomicAdd(&g_cardg[b][t-17], s_acc[t]);
}

// ------------- boundary weight, packed with label into one int -------------
__global__ void __launch_bounds__(256) boundary_kernel(const int* __restrict__ lab) {
    int idx = blockIdx.x * blockDim.x + threadIdx.x;
    if (idx >= NTOT) return;
    int v = idx & (NVOX - 1);
    int d = v >> 14;
    int r = v & 16383;
    int h = r >> 7;
    int x = r & 127;
    const int* Lb = lab + (size_t)(idx >> 20) * NVOX;
    int c0 = Lb[v];
    bool diff = false;
#pragma unroll
    for (int dd = -1; dd <= 1; dd++) {
        int zd = min(max(d + dd, 0), DD - 1);
#pragma unroll
        for (int dh = -1; dh <= 1; dh++) {
            int zh = min(max(h + dh, 0), HH - 1);
#pragma unroll
            for (int dx = -1; dx <= 1; dx++) {
                int zx = min(max(x + dx, 0), WW - 1);
                diff |= (Lb[(zd << 14) + (zh << 7) + zx] != c0);
            }
        }
    }
    g_packed[idx] = c0 | (diff ? 0x80000000 : 0);
}

// ---------------- pass A: weighted segment sums (4 channels/group) ----------
#define SEG_CH 4
__global__ void __launch_bounds__(256) segstat_kernel(const float* __restrict__ embed) {
    int b = blockIdx.y;
    int g = blockIdx.z;                 // channel group: channels [4g, 4g+4)
    __shared__ float s_cnum[NSEG][SEG_CH + 1];
    __shared__ float s_wsum[NSEG], s_cnt[NSEG];
    for (int j = threadIdx.x; j < NSEG*(SEG_CH+1); j += blockDim.x) (&s_cnum[0][0])[j] = 0.f;
    if (threadIdx.x < NSEG) { s_wsum[threadIdx.x] = 0.f; s_cnt[threadIdx.x] = 0.f; }
    __syncthreads();

    const float4* eb = (const float4*)(embed + (size_t)b * NE * NVOX + (size_t)g * SEG_CH * NVOX);
    const int4*   pb = (const int4*)(g_packed + (size_t)b * NVOX);

    int stride = gridDim.x * blockDim.x;
    for (int i = blockIdx.x * blockDim.x + threadIdx.x; i < NVOX/4; i += stride) {
        float4 e4[SEG_CH];
#pragma unroll
        for (int c = 0; c < SEG_CH; c++) e4[c] = eb[(size_t)c * (NVOX/4) + i];
        int4 p4 = pb[i];
#pragma unroll
        for (int j = 0; j < 4; j++) {
            int p = (j==0) ? p4.x : (j==1) ? p4.y : (j==2) ? p4.z : p4.w;
            int l = p & 0x7fffffff;
            float wv = (p < 0) ? 10.f : 1.f;
            if (g == 0) {
                atomicAdd(&s_wsum[l], wv);
                atomicAdd(&s_cnt[l], 1.f);
            }
#pragma unroll
            for (int c = 0; c < SEG_CH; c++) {
                float ev = (j==0) ? e4[c].x : (j==1) ? e4[c].y : (j==2) ? e4[c].z : e4[c].w;
                atomicAdd(&s_cnum[l][c], ev * wv);
            }
        }
    }
    __syncthreads();
    if (g == 0) {
        for (int j = threadIdx.x; j < NSEG; j += blockDim.x) {
            atomicAdd(&g_wsum[b][j], s_wsum[j]);
            atomicAdd(&g_cnt[b][j],  s_cnt[j]);
        }
    }
    for (int j = threadIdx.x; j < NSEG*SEG_CH; j += blockDim.x) {
        int k = j / SEG_CH, c = j % SEG_CH;
        atomicAdd(&g_cnum[b][k][g*SEG_CH + c], s_cnum[k][c]);
    }
}

// ---------------- centers + push + norm (tiny) ----------------
__global__ void centers_kernel() {
    int b = blockIdx.x;
    __shared__ float sc[NSEG][NE + 1];
    __shared__ int   s_present[NSEG];
    __shared__ float s_push, s_norm;
    __shared__ int   s_np;
    int tid = threadIdx.x;
    if (tid == 0) { s_push = 0.f; s_norm = 0.f; s_np = 0; }
    for (int j = tid; j < NSEG*NE; j += blockDim.x) {
        int k = j / NE, c = j % NE;
        float cen = g_cnum[b][k][c] / (g_wsum[b][k] + 1e-8f);
        g_centers[b][k][c] = cen;
        sc[k][c] = cen;
    }
    for (int k = tid; k < NSEG; k += blockDim.x) s_present[k] = (g_cnt[b][k] > 0.f) ? 1 : 0;
    __syncthreads();
    if (tid == 0) {
        int np = 0;
        for (int k = 1; k < NSEG; k++) np += s_present[k];
        s_np = np;
    }
    float pacc = 0.f;
    for (int p = tid; p < 120; p += blockDim.x) {
        int i = 1, rem = p;
        while (rem >= (NSEG - 1) - i) { rem -= (NSEG - 1) - i; i++; }
        int jj = i + 1 + rem;
        float ds = 0.f;
#pragma unroll
        for (int c = 0; c < NE; c++) { float dv = sc[i][c] - sc[jj][c]; ds += dv * dv; }
        float pw = sqrtf(ds);
        float tt = fmaxf(3.0f - pw, 0.f);
        if (s_present[i] && s_present[jj]) pacc += tt * tt;
    }
    atomicAdd(&s_push, pacc);
    float nacc = 0.f;
    for (int k = 1 + tid; k < NSEG; k += blockDim.x) {
        if (s_present[k]) {
            float ds = 0.f;
#pragma unroll
            for (int c = 0; c < NE; c++) ds += sc[k][c] * sc[k][c];
            nacc += sqrtf(ds);
        }
    }
    atomicAdd(&s_norm, nacc);
    __syncthreads();
    if (tid == 0) {
        float np = (float)s_np;
        float npairs = np * (np - 1.f) * 0.5f;
        g_push[b]  = (npairs > 0.f) ? s_push / fmaxf(npairs, 1.f) : 0.f;
        g_normv[b] = (np > 0.f)     ? s_norm / fmaxf(np, 1.f)     : 0.f;
        g_val[b]   = (np > 0.f) ? 1.f : 0.f;
    }
}

// ---------------- pass B: pull ----------------
__global__ void __launch_bounds__(256, 3) pull_kernel(const float* __restrict__ embed) {
    int b = blockIdx.y;
    __shared__ float sc[NSEG][NE + 1];
    __shared__ float s_pull[NSEG];
    for (int j = threadIdx.x; j < NSEG*NE; j += blockDim.x)
        sc[j / NE][j % NE] = g_centers[b][j / NE][j % NE];
    for (int j = threadIdx.x; j < NSEG; j += blockDim.x) s_pull[j] = 0.f;
    __syncthreads();

    const float4* eb = (const float4*)(embed + (size_t)b * NE * NVOX);
    const int4*   pb = (const int4*)(g_packed + (size_t)b * NVOX);

    int stride = gridDim.x * blockDim.x;
    for (int i = blockIdx.x * blockDim.x + threadIdx.x; i < NVOX/4; i += stride) {
        int4 p4 = pb[i];
        int   lv[4]; float wv[4]; float ds[4];
#pragma unroll
        for (int j = 0; j < 4; j++) {
            int p = (j==0) ? p4.x : (j==1) ? p4.y : (j==2) ? p4.z : p4.w;
            lv[j] = p & 0x7fffffff;
            wv[j] = (p < 0) ? 10.f : 1.f;
            ds[j] = 0.f;
        }
        // two halves of 8 channels to limit register pressure
#pragma unroll
        for (int half = 0; half < 2; half++) {
            float4 e4[8];
#pragma unroll
            for (int c = 0; c < 8; c++)
                e4[c] = eb[(size_t)(half*8 + c) * (NVOX/4) + i];
#pragma unroll
            for (int c = 0; c < 8; c++) {
                int cc = half*8 + c;
#pragma unroll
                for (int j = 0; j < 4; j++) {
                    float ev = (j==0) ? e4[c].x : (j==1) ? e4[c].y : (j==2) ? e4[c].z : e4[c].w;
                    float dv = ev - sc[lv[j]][cc];
                    ds[j] += dv * dv;
                }
            }
        }
#pragma unroll
        for (int j = 0; j < 4; j++) {
            float dist = sqrtf(ds[j]);
            float tt = fmaxf(dist - 0.5f, 0.f);
            atomicAdd(&s_pull[lv[j]], tt * tt * wv[j]);
        }
    }
    __syncthreads();
    for (int j = threadIdx.x; j < NSEG; j += blockDim.x)
        atomicAdd(&g_pull[b][j], s_pull[j]);
}

// ---------------- final combine ----------------
__global__ void final_kernel(float* __restrict__ out) {
    if (threadIdx.x != 0 || blockIdx.x != 0) return;
    float Nf = (float)NTOT;
    float ce = g_nll / Nf;

    float dsum = 0.f;
    for (int b = 0; b < BATCH; b++)
        for (int c = 0; c < NC; c++)
            dsum += (2.0f * g_inter[b][c] + 1e-5f) /
                    (g_cardp[b][c] + g_cardg[b][c] + 1e-5f);
    float dice = 1.0f - dsum / (float)(BATCH * NC);

    float lp = 0.f;
    for (int b = 0; b < BATCH; b++)
        for (int k = 1; k < NSEG; k++)
            if (g_cnt[b][k] > 0.f)
                lp += g_pull[b][k] / fmaxf(g_cnt[b][k], 1.f);

    float push = 0.f, nrm = 0.f, val = 0.f;
    for (int b = 0; b < BATCH; b++) { push += g_push[b]; nrm += g_normv[b]; val += g_val[b]; }

    float ins = (1.0f * lp + 1.0f * push + 0.001f * nrm) / fmaxf(val, 1.f);
    float sem = ce + dice;
    out[0] = sem + ins;
    out[1] = sem;
    out[2] = ce;
    out[3] = dice;
    out[4] = ins;
}

// ---------------- launch ----------------
extern "C" void kernel_launch(void* const* d_in, const int* in_sizes, int n_in,
                              void* d_out, int out_size) {
    const float* sem = (const float*)d_in[0];
    const float* emb = (const float*)d_in[1];
    const int*   cls = (const int*)d_in[2];
    const int*   lab = (const int*)d_in[3];
    float* out = (float*)d_out;

    zero_kernel<<<3, 256>>>();

    dim3 g1(296, BATCH);
    ce_dice_kernel<<<g1, 256>>>(sem, cls);

    boundary_kernel<<<NTOT / 256, 256>>>(lab);

    dim3 g2(148, BATCH, NE / SEG_CH);
    segstat_kernel<<<g2, 256>>>(emb);

    centers_kernel<<<BATCH, 128>>>();

    dim3 g3(296, BATCH);
    pull_kernel<<<g3, 256>>>(emb);

    final_kernel<<<1, 32>>>(out);
}